// round 2
// baseline (speedup 1.0000x reference)
#include <cuda_runtime.h>
#include <cstdint>

// CRF forward log-partition. B=512, T=1024, L=64.
// One warp per batch; probability-domain recurrence:
//   p_{t+1} = (E @ p_t) .* exp(logit_t),  E = exp(trans) resident in registers.
// Exact power-of-2 rescale every 4 steps (growth bounded by ~2^53 per group).
// logZ = ktot*ln2 + log( sum_j p[j] * exp(trans[63,j]) ).

#define CRF_B 512
#define CRF_T 1024
#define CRF_L 64
#define C_LOG2E 1.4426950408889634f
#define C_LN2   0.6931471805599453f

using u64 = unsigned long long;

__device__ __forceinline__ float ex2f(float x) {
    float r; asm("ex2.approx.f32 %0, %1;" : "=f"(r) : "f"(x)); return r;
}
__device__ __forceinline__ u64 packf2(float lo, float hi) {
    u64 r; asm("mov.b64 %0, {%1, %2};" : "=l"(r) : "f"(lo), "f"(hi)); return r;
}
__device__ __forceinline__ void unpackf2(u64 v, float& lo, float& hi) {
    asm("mov.b64 {%0, %1}, %2;" : "=f"(lo), "=f"(hi) : "l"(v));
}
#define FMA2(acc, a, b) \
    asm("fma.rn.f32x2 %0, %1, %2, %0;" : "+l"(acc) : "l"(a), "l"(b))
#define ADD2(acc, a) \
    asm("add.rn.f32x2 %0, %0, %1;" : "+l"(acc) : "l"(a))

__device__ __forceinline__ float2 eexp(float2 lg) {
    return make_float2(ex2f(lg.x * C_LOG2E), ex2f(lg.y * C_LOG2E));
}

// One CRF step. Reads all 64 p values from sp_r (16x LDS.128 broadcast),
// writes this lane's new pair to sp_w. el = precomputed exp(logit) pair.
template <bool RESCALE>
__device__ __forceinline__ void crf_step(
    float2 el,
    const u64 (&Ea)[32], const u64 (&Eb)[32],
    const ulonglong2* __restrict__ sp_r,   // 16 entries = 64 p values
    u64* __restrict__ sp_w,                // 32 entries (pair per lane)
    int lane, int& ktot)
{
    u64 a[4] = {0ull, 0ull, 0ull, 0ull};
    u64 b[4] = {0ull, 0ull, 0ull, 0ull};
#pragma unroll
    for (int q = 0; q < 16; q++) {
        ulonglong2 pv = sp_r[q];           // pairs 2q (x) and 2q+1 (y)
        const int j0 = 2 * q, j1 = 2 * q + 1;
        FMA2(a[j0 & 3], Ea[j0], pv.x);
        FMA2(b[j0 & 3], Eb[j0], pv.x);
        FMA2(a[j1 & 3], Ea[j1], pv.y);
        FMA2(b[j1 & 3], Eb[j1], pv.y);
    }
    ADD2(a[0], a[1]); ADD2(a[2], a[3]); ADD2(a[0], a[2]);
    ADD2(b[0], b[1]); ADD2(b[2], b[3]); ADD2(b[0], b[2]);
    float ax, ay, bx, by;
    unpackf2(a[0], ax, ay);
    unpackf2(b[0], bx, by);
    float pA = (ax + ay) * el.x;           // new p[2*lane]
    float pB = (bx + by) * el.y;           // new p[2*lane+1]

    if (RESCALE) {
        float m = fmaxf(pA, pB);           // p > 0: uint compare == float compare
        unsigned mu = __reduce_max_sync(0xffffffffu, __float_as_uint(m));
        int k = (int)(mu >> 23) - 127;
        ktot += k;
        float s = __int_as_float((127 - k) << 23);   // exact 2^-k
        pA *= s; pB *= s;
    }

    sp_w[lane] = packf2(pA, pB);
    __syncwarp();
}

__global__ void __launch_bounds__(128)
crf_fwd_kernel(const float* __restrict__ logits,
               const int*   __restrict__ lens,
               const float* __restrict__ trans,
               float*       __restrict__ out)
{
    __shared__ __align__(16) u64 sp[4][2][32];   // [warp][buffer][pair]

    const int w    = threadIdx.x >> 5;
    const int lane = threadIdx.x & 31;
    const int b    = blockIdx.x * 4 + w;         // grid=128 -> b < 512

    const ulonglong2* rd0 = reinterpret_cast<const ulonglong2*>(sp[w][0]);
    const ulonglong2* rd1 = reinterpret_cast<const ulonglong2*>(sp[w][1]);
    u64* wr0 = sp[w][0];
    u64* wr1 = sp[w][1];

    // ---- E = exp(trans), rows 2*lane and 2*lane+1, packed f32x2 ----
    u64 Ea[32], Eb[32];
    const float* ra = trans + (2 * lane)     * CRF_L;
    const float* rb = trans + (2 * lane + 1) * CRF_L;
#pragma unroll
    for (int jj = 0; jj < 32; jj++) {
        Ea[jj] = packf2(expf(ra[2 * jj]), expf(ra[2 * jj + 1]));
        Eb[jj] = packf2(expf(rb[2 * jj]), expf(rb[2 * jj + 1]));
    }
    const float2 e63 = make_float2(expf(trans[63 * CRF_L + 2 * lane]),
                                   expf(trans[63 * CRF_L + 2 * lane + 1]));

    // ---- init: delta at start label 62 ----
    wr0[lane] = packf2((2 * lane == 62) ? 1.0f : 0.0f,
                       (2 * lane + 1 == 62) ? 1.0f : 0.0f);
    __syncwarp();

    int ktot = 0;
    const int len = lens[b];

    const float2* lgp =
        reinterpret_cast<const float2*>(logits + (size_t)b * CRF_T * CRF_L) + lane;

    // 4-deep prefetch with exp(logit) precomputed off the critical path.
    float2 e0, e1, e2, e3;
    if (len > 0) e0 = eexp(__ldg(lgp));
    if (len > 1) e1 = eexp(__ldg(lgp + 32));
    if (len > 2) e2 = eexp(__ldg(lgp + 64));
    if (len > 3) e3 = eexp(__ldg(lgp + 96));

    int t = 0;
    for (; t + 4 <= len; t += 4) {       // p in buffer 0 at loop top
        float2 g;
        g = e0; if (t + 4 < len) e0 = eexp(__ldg(lgp + (size_t)(t + 4) * 32));
        crf_step<false>(g, Ea, Eb, rd0, wr1, lane, ktot);
        g = e1; if (t + 5 < len) e1 = eexp(__ldg(lgp + (size_t)(t + 5) * 32));
        crf_step<false>(g, Ea, Eb, rd1, wr0, lane, ktot);
        g = e2; if (t + 6 < len) e2 = eexp(__ldg(lgp + (size_t)(t + 6) * 32));
        crf_step<false>(g, Ea, Eb, rd0, wr1, lane, ktot);
        g = e3; if (t + 7 < len) e3 = eexp(__ldg(lgp + (size_t)(t + 7) * 32));
        crf_step<true >(g, Ea, Eb, rd1, wr0, lane, ktot);
    }

    int buf = 0;
    for (; t < len; ++t) {               // <=3 remainder steps, no rescale needed
        float2 g = eexp(__ldg(lgp + (size_t)t * 32));
        if (buf == 0) crf_step<false>(g, Ea, Eb, rd0, wr1, lane, ktot);
        else          crf_step<false>(g, Ea, Eb, rd1, wr0, lane, ktot);
        buf ^= 1;
    }

    // ---- finalize: logZ = ktot*ln2 + log( sum_j p[j]*E[63,j] ) ----
    float px, py;
    unpackf2((buf == 0 ? wr0 : wr1)[lane], px, py);
    float part = e63.x * px + e63.y * py;
#pragma unroll
    for (int o = 16; o > 0; o >>= 1)
        part += __shfl_xor_sync(0xffffffffu, part, o);
    if (lane == 0)
        out[b] = (float)ktot * C_LN2 + __logf(part);
}

extern "C" void kernel_launch(void* const* d_in, const int* in_sizes, int n_in,
                              void* d_out, int out_size)
{
    const float* logits = (const float*)d_in[0];   // [512,1024,64] f32
    const int*   lens   = (const int*)  d_in[1];   // [512] i32
    const float* trans  = (const float*)d_in[2];   // [64,64] f32
    float* out = (float*)d_out;                    // [512] f32

    crf_fwd_kernel<<<CRF_B / 4, 128>>>(logits, lens, trans, out);
}